// round 2
// baseline (speedup 1.0000x reference)
#include <cuda_runtime.h>
#include <cuda_bf16.h>

// Problem shape (fixed)
#define BB 4
#define LL 512
#define DD 768
#define WW 12
#define TWOD (2*DD)
#define THREED (3*DD)
#define BL (BB*LL)          // 2048
#define MOUT (BB*LL*WW)     // 24576
#define WD (WW*DD)          // 9216

// Scratch (device globals; no allocation allowed)
__device__ float g_cwt[(long)WW*DD*DD];        // [k][o][c]  28.3MB
__device__ float g_prelu[(long)BL*TWOD];       // relu(h@proj_w^T + b)  12.6MB
__device__ float g_G[(long)BL*WD];             // per-k conv contributions 75.5MB
__device__ float g_convrelu[(long)MOUT*DD];    // relu(cumsum)  75.5MB
__device__ float g_SA[(long)BL*DD];            // relu(start_rep)@W1^T
__device__ float g_SB[(long)BL*DD];            // relu(end_rep)@W2^T
__device__ int   g_is64;

// ---------------------------------------------------------------------------
// span_idx dtype detector: int64 layout has all odd int32 words == 0
// (values are in [0,512)). int32 layout has ~24576 random values there.
__global__ void detect_idx_kernel(const int* __restrict__ p, int nwords) {
    __shared__ int any;
    if (threadIdx.x == 0) any = 0;
    __syncthreads();
    int found = 0;
    for (int i = threadIdx.x; 2 * i + 1 < nwords; i += blockDim.x)
        found |= (p[2 * i + 1] != 0);
    if (found) atomicOr(&any, 1);
    __syncthreads();
    if (threadIdx.x == 0) g_is64 = (any == 0) ? 1 : 0;
}

// ---------------------------------------------------------------------------
// conv_w [o, c, k] (k fastest) -> cwt [k, o, c]  (c fastest; GEMM-friendly)
__global__ void transpose_cw_kernel(const float* __restrict__ cw, float* __restrict__ cwt) {
    int idx = blockIdx.x * blockDim.x + threadIdx.x;   // o*DD + c
    if (idx >= DD * DD) return;
    int o = idx / DD, c = idx % DD;
    const float* src = cw + (long)idx * WW;            // 12 consecutive floats
#pragma unroll
    for (int k = 0; k < WW; k++)
        cwt[(long)k * DD * DD + (long)o * DD + c] = src[k];
}

// ---------------------------------------------------------------------------
// conv_span[b,l,k,o] = sum_{j<=k, l+j<L} G[b,l+j,j,o]; store relu
__global__ void cumsum_relu_kernel(const float* __restrict__ G, float* __restrict__ out) {
    long id = (long)blockIdx.x * blockDim.x + threadIdx.x;
    if (id >= (long)BL * DD) return;
    int o  = (int)(id % DD);
    int bl = (int)(id / DD);
    int l  = bl % LL;
    int bt = bl - l;            // b*LL
    float s = 0.f;
#pragma unroll
    for (int k = 0; k < WW; k++) {
        int t = l + k;
        if (t < LL) s += G[((long)(bt + t) * WW + k) * DD + o];
        out[((long)bl * WW + k) * DD + o] = fmaxf(s, 0.f);
    }
}

// ---------------------------------------------------------------------------
// Generic SGEMM:  C[m,n] = sum_k A[m*lda+k] * B[n*ldb+k]
// EPI: 0 = plain store, 1 = +bias[n], relu, 2 = fused final epilogue
#define BM 128
#define BN 128
#define BKK 16
#define TM 8
#define TN 8

template <int EPI>
__global__ __launch_bounds__(256)
void gemm_nt_kernel(const float* __restrict__ A, int lda,
                    const float* __restrict__ B, int ldb,
                    float* __restrict__ C, int ldc, int K,
                    const float* __restrict__ bias,
                    const float* __restrict__ SA,
                    const float* __restrict__ SB,
                    const int* __restrict__ span32) {
    __shared__ float As[BKK][BM];
    __shared__ float Bs[BKK][BN];

    const int tid = threadIdx.x;
    const int m0 = blockIdx.y * BM;
    const int n0 = blockIdx.x * BN;
    const int tx = tid & 15;       // N dir (16)
    const int ty = tid >> 4;       // M dir (16)

    float acc[TM][TN];
#pragma unroll
    for (int i = 0; i < TM; i++)
#pragma unroll
        for (int j = 0; j < TN; j++) acc[i][j] = 0.f;

    const float* Ab = A + (long)m0 * lda;
    const float* Bb = B + (long)n0 * ldb;

    for (int k0 = 0; k0 < K; k0 += BKK) {
#pragma unroll
        for (int s = 0; s < 2; s++) {
            int slot = tid + 256 * s;
            int row = slot >> 2;
            int cg  = slot & 3;
            float4 va = *(const float4*)(Ab + (long)row * lda + k0 + cg * 4);
            As[cg * 4 + 0][row] = va.x;
            As[cg * 4 + 1][row] = va.y;
            As[cg * 4 + 2][row] = va.z;
            As[cg * 4 + 3][row] = va.w;
            float4 vb = *(const float4*)(Bb + (long)row * ldb + k0 + cg * 4);
            Bs[cg * 4 + 0][row] = vb.x;
            Bs[cg * 4 + 1][row] = vb.y;
            Bs[cg * 4 + 2][row] = vb.z;
            Bs[cg * 4 + 3][row] = vb.w;
        }
        __syncthreads();
#pragma unroll
        for (int k = 0; k < BKK; k++) {
            float4 a0 = *(const float4*)&As[k][ty * TM];
            float4 a1 = *(const float4*)&As[k][ty * TM + 4];
            float4 b0 = *(const float4*)&Bs[k][tx * TN];
            float4 b1 = *(const float4*)&Bs[k][tx * TN + 4];
            float a[TM] = {a0.x, a0.y, a0.z, a0.w, a1.x, a1.y, a1.z, a1.w};
            float b[TN] = {b0.x, b0.y, b0.z, b0.w, b1.x, b1.y, b1.z, b1.w};
#pragma unroll
            for (int i = 0; i < TM; i++)
#pragma unroll
                for (int j = 0; j < TN; j++)
                    acc[i][j] = fmaf(a[i], b[j], acc[i][j]);
        }
        __syncthreads();
    }

    const int ncol = n0 + tx * TN;

    if (EPI == 0) {
#pragma unroll
        for (int i = 0; i < TM; i++) {
            float* crow = C + (long)(m0 + ty * TM + i) * ldc + ncol;
            *(float4*)(crow)     = make_float4(acc[i][0], acc[i][1], acc[i][2], acc[i][3]);
            *(float4*)(crow + 4) = make_float4(acc[i][4], acc[i][5], acc[i][6], acc[i][7]);
        }
    } else if (EPI == 1) {
        float4 bv0 = *(const float4*)(bias + ncol);
        float4 bv1 = *(const float4*)(bias + ncol + 4);
        float bb[TN] = {bv0.x, bv0.y, bv0.z, bv0.w, bv1.x, bv1.y, bv1.z, bv1.w};
#pragma unroll
        for (int i = 0; i < TM; i++) {
            float* crow = C + (long)(m0 + ty * TM + i) * ldc + ncol;
            float v[TN];
#pragma unroll
            for (int j = 0; j < TN; j++) v[j] = fmaxf(acc[i][j] + bb[j], 0.f);
            *(float4*)(crow)     = make_float4(v[0], v[1], v[2], v[3]);
            *(float4*)(crow + 4) = make_float4(v[4], v[5], v[6], v[7]);
        }
    } else {  // EPI == 2 : out = relu(acc + SA[gather] + SB[gather] + bias)
        const int is64 = g_is64;
        float4 bv0 = *(const float4*)(bias + ncol);
        float4 bv1 = *(const float4*)(bias + ncol + 4);
        float bb[TN] = {bv0.x, bv0.y, bv0.z, bv0.w, bv1.x, bv1.y, bv1.z, bv1.w};
#pragma unroll
        for (int i = 0; i < TM; i++) {
            int m = m0 + ty * TM + i;                 // row = b*L*W + l*W + w
            int bidx = m / (LL * WW);
            int sw, ew;
            if (is64) {
                sw = span32[(long)m * 4];
                ew = span32[(long)m * 4 + 2];
            } else {
                sw = span32[(long)m * 2];
                ew = span32[(long)m * 2 + 1];
            }
            sw = min(max(sw, 0), LL - 1);
            ew = min(max(ew, 0), LL - 1);
            const float* sa = SA + ((long)bidx * LL + sw) * DD + ncol;
            const float* sb = SB + ((long)bidx * LL + ew) * DD + ncol;
            float4 s0 = *(const float4*)(sa);
            float4 s1 = *(const float4*)(sa + 4);
            float4 e0 = *(const float4*)(sb);
            float4 e1 = *(const float4*)(sb + 4);
            float ss[TN] = {s0.x, s0.y, s0.z, s0.w, s1.x, s1.y, s1.z, s1.w};
            float ee[TN] = {e0.x, e0.y, e0.z, e0.w, e1.x, e1.y, e1.z, e1.w};
            float v[TN];
#pragma unroll
            for (int j = 0; j < TN; j++)
                v[j] = fmaxf(acc[i][j] + ss[j] + ee[j] + bb[j], 0.f);
            float* crow = C + (long)m * ldc + ncol;
            *(float4*)(crow)     = make_float4(v[0], v[1], v[2], v[3]);
            *(float4*)(crow + 4) = make_float4(v[4], v[5], v[6], v[7]);
        }
    }
}

// ---------------------------------------------------------------------------
extern "C" void kernel_launch(void* const* d_in, const int* in_sizes, int n_in,
                              void* d_out, int out_size) {
    const float* h       = (const float*)d_in[0];
    const int*   span32  = (const int*)d_in[1];   // int32 or int64 (detected)
    const float* proj_w  = (const float*)d_in[2];
    const float* proj_b  = (const float*)d_in[3];
    const float* conv_w  = (const float*)d_in[4];
    const float* out_w   = (const float*)d_in[5];
    const float* out_b   = (const float*)d_in[6];
    float*       out     = (float*)d_out;

    float *cwt, *prelu, *G, *convrelu, *SA, *SB;
    cudaGetSymbolAddress((void**)&cwt,      g_cwt);
    cudaGetSymbolAddress((void**)&prelu,    g_prelu);
    cudaGetSymbolAddress((void**)&G,        g_G);
    cudaGetSymbolAddress((void**)&convrelu, g_convrelu);
    cudaGetSymbolAddress((void**)&SA,       g_SA);
    cudaGetSymbolAddress((void**)&SB,       g_SB);

    // 0. detect span_idx dtype (device-side, graph-capturable)
    detect_idx_kernel<<<1, 256>>>(span32, BB * LL * WW * 2);

    // 1. conv_w -> cwt [k][o][c]
    transpose_cw_kernel<<<(DD * DD + 255) / 256, 256>>>(conv_w, cwt);

    // 2. prelu = relu(h @ proj_w^T + proj_b)           [BL, 2D]
    gemm_nt_kernel<1><<<dim3(TWOD / BN, BL / BM), 256>>>(
        h, DD, proj_w, DD, prelu, TWOD, DD, proj_b, nullptr, nullptr, nullptr);

    // 3. G = h @ cwt^T                                  [BL, W*D]
    gemm_nt_kernel<0><<<dim3(WD / BN, BL / BM), 256>>>(
        h, DD, cwt, DD, G, WD, DD, nullptr, nullptr, nullptr, nullptr);

    // 4. SA = prelu[:, :D] @ out_w[:, :D]^T             [BL, D]
    gemm_nt_kernel<0><<<dim3(DD / BN, BL / BM), 256>>>(
        prelu, TWOD, out_w, THREED, SA, DD, DD, nullptr, nullptr, nullptr, nullptr);

    // 5. SB = prelu[:, D:] @ out_w[:, D:2D]^T           [BL, D]
    gemm_nt_kernel<0><<<dim3(DD / BN, BL / BM), 256>>>(
        prelu + DD, TWOD, out_w + DD, THREED, SB, DD, DD, nullptr, nullptr, nullptr, nullptr);

    // 6. convrelu = relu(shifted cumsum of G)           [M_out, D]
    cumsum_relu_kernel<<<((long)BL * DD + 255) / 256, 256>>>(G, convrelu);

    // 7. out = relu(convrelu @ out_w[:,2D:]^T + gather(SA) + gather(SB) + out_b)
    gemm_nt_kernel<2><<<dim3(DD / BN, MOUT / BM), 256>>>(
        convrelu, DD, out_w + TWOD, THREED, out, DD, DD, out_b, SA, SB, span32);
}

// round 4
// speedup vs baseline: 2.3570x; 2.3570x over previous
#include <cuda_runtime.h>
#include <cuda_bf16.h>
#include <cstdint>

#define BB 4
#define LL 512
#define DD 768
#define WW 12
#define TWOD 1536
#define THREED 2304
#define BL 2048
#define MOUT 24576
#define WD 9216

// ---- scratch (device globals; no allocation allowed) ----
__device__ __align__(16) __nv_bfloat16 g_hh[(long)BL*DD],      g_hl[(long)BL*DD];
__device__ __align__(16) __nv_bfloat16 g_pwh[(long)TWOD*DD],   g_pwl[(long)TWOD*DD];
__device__ __align__(16) __nv_bfloat16 g_owh[(long)DD*THREED], g_owl[(long)DD*THREED];
__device__ __align__(16) __nv_bfloat16 g_cwth[(long)WD*DD],    g_cwtl[(long)WD*DD];
__device__ __align__(16) __nv_bfloat16 g_ph[(long)BL*TWOD],    g_pl[(long)BL*TWOD];
__device__ __align__(16) float         g_G[(long)BL*WD];
__device__ __align__(16) __nv_bfloat16 g_ch[(long)MOUT*DD],    g_cl[(long)MOUT*DD];
__device__ __align__(16) float         g_SA[(long)BL*DD],      g_SB[(long)BL*DD];
__device__ int g_is64;

// ---- PTX helpers (baseline ISA only: sm_80-class ops, valid on compute_103) ----
__device__ __forceinline__ uint32_t smem_u32(const void* p) {
    uint32_t a;
    asm("{ .reg .u64 t; cvta.to.shared.u64 t, %1; cvt.u32.u64 %0, t; }" : "=r"(a) : "l"(p));
    return a;
}
__device__ __forceinline__ void cp16(uint32_t dst, const void* src) {
    asm volatile("cp.async.cg.shared.global [%0], [%1], 16;" :: "r"(dst), "l"(src));
}
#define CP_COMMIT() asm volatile("cp.async.commit_group;" ::: "memory")
#define CP_WAIT1()  asm volatile("cp.async.wait_group 1;" ::: "memory")

#define LDSM4(r, addr) \
    asm volatile("ldmatrix.sync.aligned.m8n8.x4.shared.b16 {%0,%1,%2,%3}, [%4];" \
        : "=r"((r)[0]), "=r"((r)[1]), "=r"((r)[2]), "=r"((r)[3]) : "r"(addr))

#define MMA16816(acc, a, b0, b1) \
    asm volatile("mma.sync.aligned.m16n8k16.row.col.f32.bf16.bf16.f32 " \
        "{%0,%1,%2,%3}, {%4,%5,%6,%7}, {%8,%9}, {%0,%1,%2,%3};" \
        : "+f"((acc)[0]), "+f"((acc)[1]), "+f"((acc)[2]), "+f"((acc)[3]) \
        : "r"((a)[0]), "r"((a)[1]), "r"((a)[2]), "r"((a)[3]), "r"(b0), "r"(b1))

// ---------------------------------------------------------------------------
__global__ void detect_idx_kernel(const int* __restrict__ p, int nwords) {
    __shared__ int any;
    if (threadIdx.x == 0) any = 0;
    __syncthreads();
    int found = 0;
    for (int i = threadIdx.x; 2 * i + 1 < nwords; i += blockDim.x)
        found |= (p[2 * i + 1] != 0);
    if (found) atomicOr(&any, 1);
    __syncthreads();
    if (threadIdx.x == 0) g_is64 = (any == 0) ? 1 : 0;
}

__global__ void split_kernel(const float* __restrict__ x,
                             __nv_bfloat16* __restrict__ xh,
                             __nv_bfloat16* __restrict__ xl, long n) {
    long i = (long)blockIdx.x * blockDim.x + threadIdx.x;
    if (i >= n) return;
    float v = x[i];
    __nv_bfloat16 h = __float2bfloat16(v);
    xh[i] = h;
    xl[i] = __float2bfloat16(v - __bfloat162float(h));
}

// conv_w [o,c,k] -> cwt [k*DD+o][c] bf16 hi/lo
__global__ void transpose_cw_kernel(const float* __restrict__ cw,
                                    __nv_bfloat16* __restrict__ th,
                                    __nv_bfloat16* __restrict__ tl) {
    int idx = blockIdx.x * blockDim.x + threadIdx.x;
    if (idx >= DD * DD) return;
    int o = idx / DD, c = idx % DD;
    const float* src = cw + (long)idx * WW;
#pragma unroll
    for (int k = 0; k < WW; k++) {
        float v = src[k];
        __nv_bfloat16 h = __float2bfloat16(v);
        long off = ((long)k * DD + o) * DD + c;
        th[off] = h;
        tl[off] = __float2bfloat16(v - __bfloat162float(h));
    }
}

// shifted cumsum of G + relu -> bf16 hi/lo
__global__ void cumsum_relu_kernel(const float* __restrict__ G,
                                   __nv_bfloat16* __restrict__ ch,
                                   __nv_bfloat16* __restrict__ cl) {
    long id = (long)blockIdx.x * blockDim.x + threadIdx.x;
    if (id >= (long)BL * DD) return;
    int o  = (int)(id % DD);
    int bl = (int)(id / DD);
    int l  = bl % LL;
    int bt = bl - l;
    float s = 0.f;
#pragma unroll
    for (int k = 0; k < WW; k++) {
        int t = l + k;
        if (t < LL) s += G[((long)(bt + t) * WW + k) * DD + o];
        float v = fmaxf(s, 0.f);
        __nv_bfloat16 h = __float2bfloat16(v);
        long off = ((long)bl * WW + k) * DD + o;
        ch[off] = h;
        cl[off] = __float2bfloat16(v - __bfloat162float(h));
    }
}

// ---------------------------------------------------------------------------
// bf16 split GEMM via mma.sync:  C[m,n] = sum_k (Ah+Al)[m,k]*(Bh+Bl)[n,k]
// 3-term compensation: AhBh + AhBl + AlBh, fp32 accumulators.
// CTA tile 128x128, BK=32, 8 warps (2M x 4N), warp tile 64x32.
// smem: 4 tiles (Ah,Al,Bh,Bl) of 128 rows x 80B (32 bf16 padded), double-buffered.
#define ROWB 80
#define TILEB (128*ROWB)     // 10240
#define STAGEB (4*TILEB)     // 40960
#define SMEMB (2*STAGEB)     // 81920

template <int EPI>
__global__ __launch_bounds__(256)
void gemm_mma(const __nv_bfloat16* __restrict__ Ah, const __nv_bfloat16* __restrict__ Al, int lda,
              const __nv_bfloat16* __restrict__ Bh, const __nv_bfloat16* __restrict__ Bl, int ldb,
              float* __restrict__ C, __nv_bfloat16* __restrict__ Chi, __nv_bfloat16* __restrict__ Clo,
              int ldc, int K,
              const float* __restrict__ bias,
              const float* __restrict__ SA, const float* __restrict__ SB,
              const int* __restrict__ span32) {
    extern __shared__ char smem[];
    const uint32_t sbase = smem_u32(smem);
    const int tid = threadIdx.x, lane = tid & 31, wid = tid >> 5;
    const int wm = wid & 1, wn = wid >> 1;           // 2 x 4 warp grid
    const int m0 = blockIdx.y * 128, n0 = blockIdx.x * 128;
    const int NIT = K >> 5;

    const char* gA[4] = {
        (const char*)(Ah + (long)m0 * lda), (const char*)(Al + (long)m0 * lda),
        (const char*)(Bh + (long)n0 * ldb), (const char*)(Bl + (long)n0 * ldb) };
    const long ldbytes[4] = { (long)lda * 2, (long)lda * 2, (long)ldb * 2, (long)ldb * 2 };

    // each thread: per tile, 2 chunks of 16B (512 chunks / 256 threads)
    const int r0c = tid >> 2, kc0 = tid & 3;          // chunk tid
    const int r1c = (tid + 256) >> 2, kc1 = tid & 3;  // chunk tid+256

    auto issue_load = [&](int it) {
        const int k0b = (it << 5) * 2;                // k-offset in bytes
        const uint32_t st = sbase + (it & 1) * STAGEB;
#pragma unroll
        for (int t = 0; t < 4; t++) {
            cp16(st + t * TILEB + r0c * ROWB + kc0 * 16, gA[t] + (long)r0c * ldbytes[t] + k0b + kc0 * 16);
            cp16(st + t * TILEB + r1c * ROWB + kc1 * 16, gA[t] + (long)r1c * ldbytes[t] + k0b + kc1 * 16);
        }
    };

    float acc[4][4][4];
#pragma unroll
    for (int i = 0; i < 4; i++)
#pragma unroll
        for (int j = 0; j < 4; j++)
#pragma unroll
            for (int v = 0; v < 4; v++) acc[i][j][v] = 0.f;

    issue_load(0);
    CP_COMMIT();

    const uint32_t a_lane_off = (uint32_t)((wm * 64 + (lane & 15)) * ROWB + (lane >> 4) * 16);
    const uint32_t b_lane_off = (uint32_t)((wn * 32 + (lane & 15)) * ROWB + (lane >> 4) * 16);

    for (int it = 0; it < NIT; it++) {
        if (it + 1 < NIT) issue_load(it + 1);
        CP_COMMIT();
        CP_WAIT1();
        __syncthreads();

        const uint32_t st = sbase + (it & 1) * STAGEB;
#pragma unroll
        for (int ks = 0; ks < 2; ks++) {
            uint32_t ah[4][4], al[4][4];
#pragma unroll
            for (int mt = 0; mt < 4; mt++) {
                uint32_t addr = st + a_lane_off + mt * 16 * ROWB + ks * 32;
                LDSM4(ah[mt], addr);
                LDSM4(al[mt], addr + TILEB);
            }
            uint32_t bh[2][4], bl[2][4];
#pragma unroll
            for (int nb = 0; nb < 2; nb++) {
                uint32_t addr = st + 2 * TILEB + b_lane_off + nb * 16 * ROWB + ks * 32;
                LDSM4(bh[nb], addr);
                LDSM4(bl[nb], addr + TILEB);
            }
#pragma unroll
            for (int mt = 0; mt < 4; mt++)
#pragma unroll
                for (int nt = 0; nt < 4; nt++) {
                    const int nb = nt >> 1, sel = nt & 1;
                    MMA16816(acc[mt][nt], ah[mt], bh[nb][sel], bh[nb][sel + 2]);
                    MMA16816(acc[mt][nt], ah[mt], bl[nb][sel], bl[nb][sel + 2]);
                    MMA16816(acc[mt][nt], al[mt], bh[nb][sel], bh[nb][sel + 2]);
                }
        }
        __syncthreads();
    }

    // ---- epilogue ----
    const int qrow = lane >> 2, qcol = (lane & 3) * 2;
    const int is64 = (EPI == 2) ? g_is64 : 0;

#pragma unroll
    for (int mt = 0; mt < 4; mt++) {
        const int r0 = m0 + wm * 64 + mt * 16 + qrow;
        const int r1 = r0 + 8;

        int sw0 = 0, ew0 = 0, sw1 = 0, ew1 = 0, boff = 0;
        const float *sa0 = nullptr, *sb0 = nullptr, *sa1 = nullptr, *sb1 = nullptr;
        if (EPI == 2) {
            if (is64) {
                sw0 = span32[(long)r0 * 4]; ew0 = span32[(long)r0 * 4 + 2];
                sw1 = span32[(long)r1 * 4]; ew1 = span32[(long)r1 * 4 + 2];
            } else {
                sw0 = span32[(long)r0 * 2]; ew0 = span32[(long)r0 * 2 + 1];
                sw1 = span32[(long)r1 * 2]; ew1 = span32[(long)r1 * 2 + 1];
            }
            sw0 = min(max(sw0, 0), LL - 1); ew0 = min(max(ew0, 0), LL - 1);
            sw1 = min(max(sw1, 0), LL - 1); ew1 = min(max(ew1, 0), LL - 1);
            boff = (r0 / (LL * WW)) * LL;   // r0, r1 always in same batch (16 | LL*WW)
            sa0 = SA + (long)(boff + sw0) * DD; sb0 = SB + (long)(boff + ew0) * DD;
            sa1 = SA + (long)(boff + sw1) * DD; sb1 = SB + (long)(boff + ew1) * DD;
        }

#pragma unroll
        for (int nt = 0; nt < 4; nt++) {
            const int gc = n0 + wn * 32 + nt * 8 + qcol;
            const float* a = acc[mt][nt];
            if (EPI == 0) {
                *(float2*)(C + (long)r0 * ldc + gc) = make_float2(a[0], a[1]);
                *(float2*)(C + (long)r1 * ldc + gc) = make_float2(a[2], a[3]);
            } else if (EPI == 1) {
                float2 b = *(const float2*)(bias + gc);
                float v0 = fmaxf(a[0] + b.x, 0.f), v1 = fmaxf(a[1] + b.y, 0.f);
                float v2 = fmaxf(a[2] + b.x, 0.f), v3 = fmaxf(a[3] + b.y, 0.f);
                __nv_bfloat162 h01 = __floats2bfloat162_rn(v0, v1);
                __nv_bfloat162 h23 = __floats2bfloat162_rn(v2, v3);
                __nv_bfloat162 l01 = __floats2bfloat162_rn(v0 - __bfloat162float(h01.x),
                                                           v1 - __bfloat162float(h01.y));
                __nv_bfloat162 l23 = __floats2bfloat162_rn(v2 - __bfloat162float(h23.x),
                                                           v3 - __bfloat162float(h23.y));
                *(__nv_bfloat162*)(Chi + (long)r0 * ldc + gc) = h01;
                *(__nv_bfloat162*)(Chi + (long)r1 * ldc + gc) = h23;
                *(__nv_bfloat162*)(Clo + (long)r0 * ldc + gc) = l01;
                *(__nv_bfloat162*)(Clo + (long)r1 * ldc + gc) = l23;
            } else {
                float2 b  = *(const float2*)(bias + gc);
                float2 s0 = *(const float2*)(sa0 + gc), e0 = *(const float2*)(sb0 + gc);
                float2 s1 = *(const float2*)(sa1 + gc), e1 = *(const float2*)(sb1 + gc);
                float2 o0 = make_float2(fmaxf(a[0] + s0.x + e0.x + b.x, 0.f),
                                        fmaxf(a[1] + s0.y + e0.y + b.y, 0.f));
                float2 o1 = make_float2(fmaxf(a[2] + s1.x + e1.x + b.x, 0.f),
                                        fmaxf(a[3] + s1.y + e1.y + b.y, 0.f));
                *(float2*)(C + (long)r0 * ldc + gc) = o0;
                *(float2*)(C + (long)r1 * ldc + gc) = o1;
            }
        }
    }
}

// ---------------------------------------------------------------------------
extern "C" void kernel_launch(void* const* d_in, const int* in_sizes, int n_in,
                              void* d_out, int out_size) {
    const float* h      = (const float*)d_in[0];
    const int*   span32 = (const int*)d_in[1];
    const float* proj_w = (const float*)d_in[2];
    const float* proj_b = (const float*)d_in[3];
    const float* conv_w = (const float*)d_in[4];
    const float* out_w  = (const float*)d_in[5];
    const float* out_b  = (const float*)d_in[6];
    float*       out    = (float*)d_out;

    __nv_bfloat16 *hh, *hl, *pwh, *pwl, *owh, *owl, *cwth, *cwtl, *ph, *pl, *ch, *cl;
    float *G, *SA, *SB;
    cudaGetSymbolAddress((void**)&hh,   g_hh);   cudaGetSymbolAddress((void**)&hl,   g_hl);
    cudaGetSymbolAddress((void**)&pwh,  g_pwh);  cudaGetSymbolAddress((void**)&pwl,  g_pwl);
    cudaGetSymbolAddress((void**)&owh,  g_owh);  cudaGetSymbolAddress((void**)&owl,  g_owl);
    cudaGetSymbolAddress((void**)&cwth, g_cwth); cudaGetSymbolAddress((void**)&cwtl, g_cwtl);
    cudaGetSymbolAddress((void**)&ph,   g_ph);   cudaGetSymbolAddress((void**)&pl,   g_pl);
    cudaGetSymbolAddress((void**)&ch,   g_ch);   cudaGetSymbolAddress((void**)&cl,   g_cl);
    cudaGetSymbolAddress((void**)&G,    g_G);
    cudaGetSymbolAddress((void**)&SA,   g_SA);   cudaGetSymbolAddress((void**)&SB,   g_SB);

    cudaFuncSetAttribute((const void*)gemm_mma<0>, cudaFuncAttributeMaxDynamicSharedMemorySize, SMEMB);
    cudaFuncSetAttribute((const void*)gemm_mma<1>, cudaFuncAttributeMaxDynamicSharedMemorySize, SMEMB);
    cudaFuncSetAttribute((const void*)gemm_mma<2>, cudaFuncAttributeMaxDynamicSharedMemorySize, SMEMB);

    // 0. span_idx dtype detection (device-side, capturable)
    detect_idx_kernel<<<1, 256>>>(span32, BB * LL * WW * 2);

    // 1. fp32 -> bf16 hi/lo conversions
    split_kernel<<<((long)BL * DD + 255) / 256, 256>>>(h, hh, hl, (long)BL * DD);
    split_kernel<<<((long)TWOD * DD + 255) / 256, 256>>>(proj_w, pwh, pwl, (long)TWOD * DD);
    split_kernel<<<((long)DD * THREED + 255) / 256, 256>>>(out_w, owh, owl, (long)DD * THREED);
    transpose_cw_kernel<<<(DD * DD + 255) / 256, 256>>>(conv_w, cwth, cwtl);

    // 2. prelu = relu(h @ proj_w^T + proj_b) -> bf16 hi/lo   [BL, 2D]
    gemm_mma<1><<<dim3(TWOD / 128, BL / 128), 256, SMEMB>>>(
        hh, hl, DD, pwh, pwl, DD, nullptr, ph, pl, TWOD, DD, proj_b, nullptr, nullptr, nullptr);

    // 3. G = h @ cwt^T  (fp32)                               [BL, W*D]
    gemm_mma<0><<<dim3(WD / 128, BL / 128), 256, SMEMB>>>(
        hh, hl, DD, cwth, cwtl, DD, G, nullptr, nullptr, WD, DD, nullptr, nullptr, nullptr, nullptr);

    // 4. SA = prelu[:, :D] @ out_w[:, :D]^T                  [BL, D]
    gemm_mma<0><<<dim3(DD / 128, BL / 128), 256, SMEMB>>>(
        ph, pl, TWOD, owh, owl, THREED, SA, nullptr, nullptr, DD, DD,
        nullptr, nullptr, nullptr, nullptr);

    // 5. SB = prelu[:, D:] @ out_w[:, D:2D]^T                [BL, D]
    gemm_mma<0><<<dim3(DD / 128, BL / 128), 256, SMEMB>>>(
        ph + DD, pl + DD, TWOD, owh + DD, owl + DD, THREED, SB, nullptr, nullptr, DD, DD,
        nullptr, nullptr, nullptr, nullptr);

    // 6. convrelu = relu(shifted cumsum of G) -> bf16 hi/lo  [M_out, D]
    cumsum_relu_kernel<<<((long)BL * DD + 255) / 256, 256>>>(G, ch, cl);

    // 7. out = relu(conv @ out_w[:,2D:]^T + gather(SA) + gather(SB) + out_b)
    gemm_mma<2><<<dim3(DD / 128, MOUT / 128), 256, SMEMB>>>(
        ch, cl, DD, owh + TWOD, owl + TWOD, THREED, out, nullptr, nullptr, DD, DD,
        out_b, SA, SB, span32);
}

// round 5
// speedup vs baseline: 2.3599x; 1.0012x over previous
#include <cuda_runtime.h>
#include <cuda_bf16.h>
#include <cstdint>

#define BB 4
#define LL 512
#define DD 768
#define WW 12
#define TWOD 1536
#define THREED 2304
#define BL 2048
#define MOUT 24576
#define WD 9216

// ---- scratch (device globals; no allocation allowed) ----
__device__ __align__(16) __nv_bfloat16 g_hh[(long)BL*DD],      g_hl[(long)BL*DD];
__device__ __align__(16) __nv_bfloat16 g_pwh[(long)TWOD*DD],   g_pwl[(long)TWOD*DD];
__device__ __align__(16) __nv_bfloat16 g_owh[(long)DD*THREED], g_owl[(long)DD*THREED];
__device__ __align__(16) __nv_bfloat16 g_cwth[(long)WD*DD],    g_cwtl[(long)WD*DD];
__device__ __align__(16) __nv_bfloat16 g_ph[(long)BL*TWOD],    g_pl[(long)BL*TWOD];
__device__ __align__(16) float         g_G[(long)BL*WD];
__device__ __align__(16) __nv_bfloat16 g_ch[(long)MOUT*DD],    g_cl[(long)MOUT*DD];
__device__ __align__(16) float         g_SA[(long)BL*DD],      g_SB[(long)BL*DD];
__device__ int g_is64;

// ---- PTX helpers (baseline ISA only: sm_80-class ops, valid on compute_103) ----
__device__ __forceinline__ uint32_t smem_u32(const void* p) {
    uint32_t a;
    asm("{ .reg .u64 t; cvta.to.shared.u64 t, %1; cvt.u32.u64 %0, t; }" : "=r"(a) : "l"(p));
    return a;
}
__device__ __forceinline__ void cp16(uint32_t dst, const void* src) {
    asm volatile("cp.async.cg.shared.global [%0], [%1], 16;" :: "r"(dst), "l"(src));
}
#define CP_COMMIT() asm volatile("cp.async.commit_group;" ::: "memory")
#define CP_WAIT1()  asm volatile("cp.async.wait_group 1;" ::: "memory")

#define LDSM4(r, addr) \
    asm volatile("ldmatrix.sync.aligned.m8n8.x4.shared.b16 {%0,%1,%2,%3}, [%4];" \
        : "=r"((r)[0]), "=r"((r)[1]), "=r"((r)[2]), "=r"((r)[3]) : "r"(addr))

#define MMA16816(acc, a, b0, b1) \
    asm volatile("mma.sync.aligned.m16n8k16.row.col.f32.bf16.bf16.f32 " \
        "{%0,%1,%2,%3}, {%4,%5,%6,%7}, {%8,%9}, {%0,%1,%2,%3};" \
        : "+f"((acc)[0]), "+f"((acc)[1]), "+f"((acc)[2]), "+f"((acc)[3]) \
        : "r"((a)[0]), "r"((a)[1]), "r"((a)[2]), "r"((a)[3]), "r"(b0), "r"(b1))

// ---------------------------------------------------------------------------
__global__ void detect_idx_kernel(const int* __restrict__ p, int nwords) {
    __shared__ int any;
    if (threadIdx.x == 0) any = 0;
    __syncthreads();
    int found = 0;
    for (int i = threadIdx.x; 2 * i + 1 < nwords; i += blockDim.x)
        found |= (p[2 * i + 1] != 0);
    if (found) atomicOr(&any, 1);
    __syncthreads();
    if (threadIdx.x == 0) g_is64 = (any == 0) ? 1 : 0;
}

__global__ void split_kernel(const float* __restrict__ x,
                             __nv_bfloat16* __restrict__ xh,
                             __nv_bfloat16* __restrict__ xl, long n) {
    long i = (long)blockIdx.x * blockDim.x + threadIdx.x;
    if (i >= n) return;
    float v = x[i];
    __nv_bfloat16 h = __float2bfloat16(v);
    xh[i] = h;
    xl[i] = __float2bfloat16(v - __bfloat162float(h));
}

// conv_w [o,c,k] -> cwt [k*DD+o][c] bf16 hi/lo
__global__ void transpose_cw_kernel(const float* __restrict__ cw,
                                    __nv_bfloat16* __restrict__ th,
                                    __nv_bfloat16* __restrict__ tl) {
    int idx = blockIdx.x * blockDim.x + threadIdx.x;
    if (idx >= DD * DD) return;
    int o = idx / DD, c = idx % DD;
    const float* src = cw + (long)idx * WW;
#pragma unroll
    for (int k = 0; k < WW; k++) {
        float v = src[k];
        __nv_bfloat16 h = __float2bfloat16(v);
        long off = ((long)k * DD + o) * DD + c;
        th[off] = h;
        tl[off] = __float2bfloat16(v - __bfloat162float(h));
    }
}

// shifted cumsum of G + relu -> bf16 hi/lo
__global__ void cumsum_relu_kernel(const float* __restrict__ G,
                                   __nv_bfloat16* __restrict__ ch,
                                   __nv_bfloat16* __restrict__ cl) {
    long id = (long)blockIdx.x * blockDim.x + threadIdx.x;
    if (id >= (long)BL * DD) return;
    int o  = (int)(id % DD);
    int bl = (int)(id / DD);
    int l  = bl % LL;
    int bt = bl - l;
    float s = 0.f;
#pragma unroll
    for (int k = 0; k < WW; k++) {
        int t = l + k;
        if (t < LL) s += G[((long)(bt + t) * WW + k) * DD + o];
        float v = fmaxf(s, 0.f);
        __nv_bfloat16 h = __float2bfloat16(v);
        long off = ((long)bl * WW + k) * DD + o;
        ch[off] = h;
        cl[off] = __float2bfloat16(v - __bfloat162float(h));
    }
}

// ---------------------------------------------------------------------------
// bf16 split GEMM via mma.sync:  C[m,n] = sum_k (Ah+Al)[m,k]*(Bh+Bl)[n,k]
// 3-term compensation: AhBh + AhBl + AlBh, fp32 accumulators.
// CTA tile 128x128, BK=32, 8 warps (2M x 4N), warp tile 64x32.
// smem: 4 tiles (Ah,Al,Bh,Bl) of 128 rows x 80B (32 bf16 padded), double-buffered.
#define ROWB 80
#define TILEB (128*ROWB)     // 10240
#define STAGEB (4*TILEB)     // 40960
#define SMEMB (2*STAGEB)     // 81920

template <int EPI>
__global__ __launch_bounds__(256)
void gemm_mma(const __nv_bfloat16* __restrict__ Ah, const __nv_bfloat16* __restrict__ Al, int lda,
              const __nv_bfloat16* __restrict__ Bh, const __nv_bfloat16* __restrict__ Bl, int ldb,
              float* __restrict__ C, __nv_bfloat16* __restrict__ Chi, __nv_bfloat16* __restrict__ Clo,
              int ldc, int K,
              const float* __restrict__ bias,
              const float* __restrict__ SA, const float* __restrict__ SB,
              const int* __restrict__ span32) {
    extern __shared__ char smem[];
    const uint32_t sbase = smem_u32(smem);
    const int tid = threadIdx.x, lane = tid & 31, wid = tid >> 5;
    const int wm = wid & 1, wn = wid >> 1;           // 2 x 4 warp grid
    const int m0 = blockIdx.y * 128, n0 = blockIdx.x * 128;
    const int NIT = K >> 5;

    const char* gA[4] = {
        (const char*)(Ah + (long)m0 * lda), (const char*)(Al + (long)m0 * lda),
        (const char*)(Bh + (long)n0 * ldb), (const char*)(Bl + (long)n0 * ldb) };
    const long ldbytes[4] = { (long)lda * 2, (long)lda * 2, (long)ldb * 2, (long)ldb * 2 };

    // each thread: per tile, 2 chunks of 16B (512 chunks / 256 threads)
    const int r0c = tid >> 2, kc0 = tid & 3;          // chunk tid
    const int r1c = (tid + 256) >> 2, kc1 = tid & 3;  // chunk tid+256

    auto issue_load = [&](int it) {
        const int k0b = (it << 5) * 2;                // k-offset in bytes
        const uint32_t st = sbase + (it & 1) * STAGEB;
#pragma unroll
        for (int t = 0; t < 4; t++) {
            cp16(st + t * TILEB + r0c * ROWB + kc0 * 16, gA[t] + (long)r0c * ldbytes[t] + k0b + kc0 * 16);
            cp16(st + t * TILEB + r1c * ROWB + kc1 * 16, gA[t] + (long)r1c * ldbytes[t] + k0b + kc1 * 16);
        }
    };

    float acc[4][4][4];
#pragma unroll
    for (int i = 0; i < 4; i++)
#pragma unroll
        for (int j = 0; j < 4; j++)
#pragma unroll
            for (int v = 0; v < 4; v++) acc[i][j][v] = 0.f;

    issue_load(0);
    CP_COMMIT();

    const uint32_t a_lane_off = (uint32_t)((wm * 64 + (lane & 15)) * ROWB + (lane >> 4) * 16);
    const uint32_t b_lane_off = (uint32_t)((wn * 32 + (lane & 15)) * ROWB + (lane >> 4) * 16);

    for (int it = 0; it < NIT; it++) {
        if (it + 1 < NIT) issue_load(it + 1);
        CP_COMMIT();
        CP_WAIT1();
        __syncthreads();

        const uint32_t st = sbase + (it & 1) * STAGEB;
#pragma unroll
        for (int ks = 0; ks < 2; ks++) {
            uint32_t ah[4][4], al[4][4];
#pragma unroll
            for (int mt = 0; mt < 4; mt++) {
                uint32_t addr = st + a_lane_off + mt * 16 * ROWB + ks * 32;
                LDSM4(ah[mt], addr);
                LDSM4(al[mt], addr + TILEB);
            }
            uint32_t bh[2][4], bl[2][4];
#pragma unroll
            for (int nb = 0; nb < 2; nb++) {
                uint32_t addr = st + 2 * TILEB + b_lane_off + nb * 16 * ROWB + ks * 32;
                LDSM4(bh[nb], addr);
                LDSM4(bl[nb], addr + TILEB);
            }
#pragma unroll
            for (int mt = 0; mt < 4; mt++)
#pragma unroll
                for (int nt = 0; nt < 4; nt++) {
                    const int nb = nt >> 1, sel = nt & 1;
                    MMA16816(acc[mt][nt], ah[mt], bh[nb][sel], bh[nb][sel + 2]);
                    MMA16816(acc[mt][nt], ah[mt], bl[nb][sel], bl[nb][sel + 2]);
                    MMA16816(acc[mt][nt], al[mt], bh[nb][sel], bh[nb][sel + 2]);
                }
        }
        __syncthreads();
    }

    // ---- epilogue ----
    const int qrow = lane >> 2, qcol = (lane & 3) * 2;
    const int is64 = (EPI == 2) ? g_is64 : 0;

#pragma unroll
    for (int mt = 0; mt < 4; mt++) {
        const int r0 = m0 + wm * 64 + mt * 16 + qrow;
        const int r1 = r0 + 8;

        int sw0 = 0, ew0 = 0, sw1 = 0, ew1 = 0, boff = 0;
        const float *sa0 = nullptr, *sb0 = nullptr, *sa1 = nullptr, *sb1 = nullptr;
        if (EPI == 2) {
            if (is64) {
                sw0 = span32[(long)r0 * 4]; ew0 = span32[(long)r0 * 4 + 2];
                sw1 = span32[(long)r1 * 4]; ew1 = span32[(long)r1 * 4 + 2];
            } else {
                sw0 = span32[(long)r0 * 2]; ew0 = span32[(long)r0 * 2 + 1];
                sw1 = span32[(long)r1 * 2]; ew1 = span32[(long)r1 * 2 + 1];
            }
            sw0 = min(max(sw0, 0), LL - 1); ew0 = min(max(ew0, 0), LL - 1);
            sw1 = min(max(sw1, 0), LL - 1); ew1 = min(max(ew1, 0), LL - 1);
            boff = (r0 / (LL * WW)) * LL;   // r0, r1 always in same batch (16 | LL*WW)
            sa0 = SA + (long)(boff + sw0) * DD; sb0 = SB + (long)(boff + ew0) * DD;
            sa1 = SA + (long)(boff + sw1) * DD; sb1 = SB + (long)(boff + ew1) * DD;
        }

#pragma unroll
        for (int nt = 0; nt < 4; nt++) {
            const int gc = n0 + wn * 32 + nt * 8 + qcol;
            const float* a = acc[mt][nt];
            if (EPI == 0) {
                *(float2*)(C + (long)r0 * ldc + gc) = make_float2(a[0], a[1]);
                *(float2*)(C + (long)r1 * ldc + gc) = make_float2(a[2], a[3]);
            } else if (EPI == 1) {
                float2 b = *(const float2*)(bias + gc);
                float v0 = fmaxf(a[0] + b.x, 0.f), v1 = fmaxf(a[1] + b.y, 0.f);
                float v2 = fmaxf(a[2] + b.x, 0.f), v3 = fmaxf(a[3] + b.y, 0.f);
                __nv_bfloat162 h01 = __floats2bfloat162_rn(v0, v1);
                __nv_bfloat162 h23 = __floats2bfloat162_rn(v2, v3);
                __nv_bfloat162 l01 = __floats2bfloat162_rn(v0 - __bfloat162float(h01.x),
                                                           v1 - __bfloat162float(h01.y));
                __nv_bfloat162 l23 = __floats2bfloat162_rn(v2 - __bfloat162float(h23.x),
                                                           v3 - __bfloat162float(h23.y));
                *(__nv_bfloat162*)(Chi + (long)r0 * ldc + gc) = h01;
                *(__nv_bfloat162*)(Chi + (long)r1 * ldc + gc) = h23;
                *(__nv_bfloat162*)(Clo + (long)r0 * ldc + gc) = l01;
                *(__nv_bfloat162*)(Clo + (long)r1 * ldc + gc) = l23;
            } else {
                float2 b  = *(const float2*)(bias + gc);
                float2 s0 = *(const float2*)(sa0 + gc), e0 = *(const float2*)(sb0 + gc);
                float2 s1 = *(const float2*)(sa1 + gc), e1 = *(const float2*)(sb1 + gc);
                float2 o0 = make_float2(fmaxf(a[0] + s0.x + e0.x + b.x, 0.f),
                                        fmaxf(a[1] + s0.y + e0.y + b.y, 0.f));
                float2 o1 = make_float2(fmaxf(a[2] + s1.x + e1.x + b.x, 0.f),
                                        fmaxf(a[3] + s1.y + e1.y + b.y, 0.f));
                *(float2*)(C + (long)r0 * ldc + gc) = o0;
                *(float2*)(C + (long)r1 * ldc + gc) = o1;
            }
        }
    }
}

// ---------------------------------------------------------------------------
extern "C" void kernel_launch(void* const* d_in, const int* in_sizes, int n_in,
                              void* d_out, int out_size) {
    const float* h      = (const float*)d_in[0];
    const int*   span32 = (const int*)d_in[1];
    const float* proj_w = (const float*)d_in[2];
    const float* proj_b = (const float*)d_in[3];
    const float* conv_w = (const float*)d_in[4];
    const float* out_w  = (const float*)d_in[5];
    const float* out_b  = (const float*)d_in[6];
    float*       out    = (float*)d_out;

    __nv_bfloat16 *hh, *hl, *pwh, *pwl, *owh, *owl, *cwth, *cwtl, *ph, *pl, *ch, *cl;
    float *G, *SA, *SB;
    cudaGetSymbolAddress((void**)&hh,   g_hh);   cudaGetSymbolAddress((void**)&hl,   g_hl);
    cudaGetSymbolAddress((void**)&pwh,  g_pwh);  cudaGetSymbolAddress((void**)&pwl,  g_pwl);
    cudaGetSymbolAddress((void**)&owh,  g_owh);  cudaGetSymbolAddress((void**)&owl,  g_owl);
    cudaGetSymbolAddress((void**)&cwth, g_cwth); cudaGetSymbolAddress((void**)&cwtl, g_cwtl);
    cudaGetSymbolAddress((void**)&ph,   g_ph);   cudaGetSymbolAddress((void**)&pl,   g_pl);
    cudaGetSymbolAddress((void**)&ch,   g_ch);   cudaGetSymbolAddress((void**)&cl,   g_cl);
    cudaGetSymbolAddress((void**)&G,    g_G);
    cudaGetSymbolAddress((void**)&SA,   g_SA);   cudaGetSymbolAddress((void**)&SB,   g_SB);

    cudaFuncSetAttribute((const void*)gemm_mma<0>, cudaFuncAttributeMaxDynamicSharedMemorySize, SMEMB);
    cudaFuncSetAttribute((const void*)gemm_mma<1>, cudaFuncAttributeMaxDynamicSharedMemorySize, SMEMB);
    cudaFuncSetAttribute((const void*)gemm_mma<2>, cudaFuncAttributeMaxDynamicSharedMemorySize, SMEMB);

    // 0. span_idx dtype detection (device-side, capturable)
    detect_idx_kernel<<<1, 256>>>(span32, BB * LL * WW * 2);

    // 1. fp32 -> bf16 hi/lo conversions
    split_kernel<<<((long)BL * DD + 255) / 256, 256>>>(h, hh, hl, (long)BL * DD);
    split_kernel<<<((long)TWOD * DD + 255) / 256, 256>>>(proj_w, pwh, pwl, (long)TWOD * DD);
    split_kernel<<<((long)DD * THREED + 255) / 256, 256>>>(out_w, owh, owl, (long)DD * THREED);
    transpose_cw_kernel<<<(DD * DD + 255) / 256, 256>>>(conv_w, cwth, cwtl);

    // 2. prelu = relu(h @ proj_w^T + proj_b) -> bf16 hi/lo   [BL, 2D]
    gemm_mma<1><<<dim3(TWOD / 128, BL / 128), 256, SMEMB>>>(
        hh, hl, DD, pwh, pwl, DD, nullptr, ph, pl, TWOD, DD, proj_b, nullptr, nullptr, nullptr);

    // 3. G = h @ cwt^T  (fp32)                               [BL, W*D]
    gemm_mma<0><<<dim3(WD / 128, BL / 128), 256, SMEMB>>>(
        hh, hl, DD, cwth, cwtl, DD, G, nullptr, nullptr, WD, DD, nullptr, nullptr, nullptr, nullptr);

    // 4. SA = prelu[:, :D] @ out_w[:, :D]^T                  [BL, D]
    gemm_mma<0><<<dim3(DD / 128, BL / 128), 256, SMEMB>>>(
        ph, pl, TWOD, owh, owl, THREED, SA, nullptr, nullptr, DD, DD,
        nullptr, nullptr, nullptr, nullptr);

    // 5. SB = prelu[:, D:] @ out_w[:, D:2D]^T                [BL, D]
    gemm_mma<0><<<dim3(DD / 128, BL / 128), 256, SMEMB>>>(
        ph + DD, pl + DD, TWOD, owh + DD, owl + DD, THREED, SB, nullptr, nullptr, DD, DD,
        nullptr, nullptr, nullptr, nullptr);

    // 6. convrelu = relu(shifted cumsum of G) -> bf16 hi/lo  [M_out, D]
    cumsum_relu_kernel<<<((long)BL * DD + 255) / 256, 256>>>(G, ch, cl);

    // 7. out = relu(conv @ out_w[:,2D:]^T + gather(SA) + gather(SB) + out_b)
    gemm_mma<2><<<dim3(DD / 128, MOUT / 128), 256, SMEMB>>>(
        ch, cl, DD, owh + TWOD, owl + TWOD, THREED, out, nullptr, nullptr, DD, DD,
        out_b, SA, SB, span32);
}